// round 8
// baseline (speedup 1.0000x reference)
#include <cuda_runtime.h>
#include <cuda_fp16.h>
#include <cuda_bf16.h>
#include <math.h>

#define N_NODES 100000
#define E_EDGES 1600000
#define CAP 80                     // padded slots per dst (max degree ~45)

// ---------------- scratch (device globals; no allocation allowed) ----------
__device__ __half g_zh[N_NODES * 32];      // z in fp16 (6.4 MB, L2-resident)
__device__ float  g_sl[N_NODES];
__device__ float  g_sr[N_NODES];
__device__ int    g_cnt[N_NODES];          // scatter cursor == degree
__device__ uint2  g_pk[N_NODES * CAP];     // padded CSR payload: (src, w)

// split two floats into (hi bf16x2, lo bf16x2); low half of reg = first elem
__device__ __forceinline__ void split2(float x0, float x1,
                                       unsigned& hi, unsigned& lo) {
    unsigned hh;
    asm("cvt.rn.bf16x2.f32 %0, %1, %2;" : "=r"(hh) : "f"(x1), "f"(x0));
    float f0 = __uint_as_float(hh << 16);          // bf16(x0) as f32 (exact)
    float f1 = __uint_as_float(hh & 0xFFFF0000u);  // bf16(x1) as f32 (exact)
    float l0 = x0 - f0, l1 = x1 - f1;
    unsigned ll;
    asm("cvt.rn.bf16x2.f32 %0, %1, %2;" : "=r"(ll) : "f"(l1), "f"(l0));
    hi = hh; lo = ll;
}

#define LDSM_X4(r0, r1, r2, r3, addr) \
    asm volatile("ldmatrix.sync.aligned.m8n8.x4.shared.b16 {%0,%1,%2,%3}, [%4];" \
        : "=r"(r0), "=r"(r1), "=r"(r2), "=r"(r3) : "r"(addr))

#define MMA_BF16(d, a0, a1, a2, a3, b0, b1) \
    asm volatile("mma.sync.aligned.m16n8k16.row.col.f32.bf16.bf16.f32 " \
        "{%0,%1,%2,%3}, {%4,%5,%6,%7}, {%8,%9}, {%0,%1,%2,%3};" \
        : "+f"(d[0]), "+f"(d[1]), "+f"(d[2]), "+f"(d[3]) \
        : "r"(a0), "r"(a1), "r"(a2), "r"(a3), "r"(b0), "r"(b1))

// ---------------------------------------------------------------------------
// Tensor-core GEMM: z = h @ fc_w^T + s_l/s_r, bf16-split (3 MMAs: h1w1 +
// h1w2 + h2w1; error ~2^-16, below fp16-z storage noise).
// Block: 128 threads = 4 warps, 64 rows; warp = 16 rows x 32 cols.
// Full K=128 staged once as bf16 hi/lo, XOR-swizzled 16B chunks:
//   h_hi/h_lo [64][128] bf16 (16KB each), wT_hi/lo [32][128] bf16 (8KB each)
//   = 48KB static smem exactly. fc_w is [n][k] row-major == wT already, so B
//   fragments come from non-trans ldmatrix (row.col B-frag trick).
// ---------------------------------------------------------------------------
__global__ __launch_bounds__(128, 4)
void gemm_kernel(const float* __restrict__ h,
                 const float* __restrict__ fc_w,
                 const float* __restrict__ attn_w) {
    __shared__ __align__(16) unsigned char smem[49152];
    unsigned char* h_hi = smem;            // 64*256B = 16384
    unsigned char* h_lo = smem + 16384;    // 16384
    unsigned char* w_hi = smem + 32768;    // 32*256B = 8192
    unsigned char* w_lo = smem + 40960;    // 8192

    int tid  = threadIdx.x;
    int lane = tid & 31;
    int wid  = tid >> 5;
    int rowbase = blockIdx.x * 64;

    // zero scatter cursors (1563*128 = 200064 >= N_NODES)
    int zid = blockIdx.x * 128 + tid;
    if (zid < N_NODES) g_cnt[zid] = 0;

    // ---- stage w (fc_w = [32][128] f32 = wT) as bf16 hi/lo, swizzled ----
    // chunk(16B) = k/8; swizzled chunk = chunk ^ (n&7); 8B half at (k%8)*2
    for (int i = tid; i < 1024; i += 128) {        // 1024 float4
        int n  = i >> 5;
        int k4 = (i & 31) * 4;
        float4 v = *(const float4*)&fc_w[n * 128 + k4];
        unsigned hi0, lo0, hi1, lo1;
        split2(v.x, v.y, hi0, lo0);
        split2(v.z, v.w, hi1, lo1);
        int off = n * 256 + (((k4 >> 3) ^ (n & 7)) << 4) + (k4 & 7) * 2;
        *(uint2*)(w_hi + off) = make_uint2(hi0, hi1);
        *(uint2*)(w_lo + off) = make_uint2(lo0, lo1);
    }

    // ---- stage h rows (64 x 128 f32) as bf16 hi/lo, swizzled ----
    for (int i = tid; i < 2048; i += 128) {        // 2048 float4
        int r  = i >> 5;
        int k4 = (i & 31) * 4;
        int grow = rowbase + r;
        float4 v = (grow < N_NODES)
                 ? *(const float4*)&h[(size_t)grow * 128 + k4]
                 : make_float4(0.f, 0.f, 0.f, 0.f);
        unsigned hi0, lo0, hi1, lo1;
        split2(v.x, v.y, hi0, lo0);
        split2(v.z, v.w, hi1, lo1);
        int off = r * 256 + (((k4 >> 3) ^ (r & 7)) << 4) + (k4 & 7) * 2;
        *(uint2*)(h_hi + off) = make_uint2(hi0, hi1);
        *(uint2*)(h_lo + off) = make_uint2(lo0, lo1);
    }
    __syncthreads();

    // ---- per-warp MMA mainloop: 16 rows x 32 cols, 8 k-steps ----
    int rb = wid * 16;
    // A ldmatrix lane geometry (x4 tiles: [r0-7,k0-7],[r8-15,k0-7],[r0-7,k8-15],[r8-15,k8-15])
    int a_row   = rb + (lane & 7) + ((lane >> 3) & 1) * 8;
    int a_kcsel = (lane >> 4) & 1;
    unsigned a_hi_base = (unsigned)__cvta_generic_to_shared(h_hi) + a_row * 256;
    unsigned a_lo_base = (unsigned)__cvta_generic_to_shared(h_lo) + a_row * 256;
    int a_sw = a_row & 7;
    // B ldmatrix lane geometry per nt-pair: n = (ntp*2 + (lane>>4&1))*8 + (lane&7)
    int b_noff = ((lane >> 4) & 1) * 8 + (lane & 7);
    int b_kcsel = (lane >> 3) & 1;
    unsigned w_hi_base = (unsigned)__cvta_generic_to_shared(w_hi);
    unsigned w_lo_base = (unsigned)__cvta_generic_to_shared(w_lo);

    float d[4][4];
#pragma unroll
    for (int nt = 0; nt < 4; nt++)
#pragma unroll
        for (int q = 0; q < 4; q++) d[nt][q] = 0.f;

#pragma unroll
    for (int ks = 0; ks < 8; ks++) {
        int akc = ks * 2 + a_kcsel;
        unsigned a_addr_off = (unsigned)((akc ^ a_sw) << 4);
        unsigned ah0, ah1, ah2, ah3, al0, al1, al2, al3;
        LDSM_X4(ah0, ah1, ah2, ah3, a_hi_base + a_addr_off);
        LDSM_X4(al0, al1, al2, al3, a_lo_base + a_addr_off);

        int bkc = ks * 2 + b_kcsel;
        unsigned bh[8], bl[8];   // [ntp*4 + reg]
#pragma unroll
        for (int ntp = 0; ntp < 2; ntp++) {
            int n = ntp * 16 + b_noff;
            unsigned boff = (unsigned)(n * 256 + ((bkc ^ (n & 7)) << 4));
            LDSM_X4(bh[ntp*4+0], bh[ntp*4+1], bh[ntp*4+2], bh[ntp*4+3], w_hi_base + boff);
            LDSM_X4(bl[ntp*4+0], bl[ntp*4+1], bl[ntp*4+2], bl[ntp*4+3], w_lo_base + boff);
        }
        // tiles within x4: {nt even: regs 0,1}, {nt odd: regs 2,3}
#pragma unroll
        for (int nt = 0; nt < 4; nt++) {
            int base = (nt >> 1) * 4 + (nt & 1) * 2;
            unsigned bh0 = bh[base], bh1 = bh[base + 1];
            unsigned bl0 = bl[base], bl1 = bl[base + 1];
            MMA_BF16(d[nt], ah0, ah1, ah2, ah3, bh0, bh1);   // h1*w1
            MMA_BF16(d[nt], ah0, ah1, ah2, ah3, bl0, bl1);   // h1*w2
            MMA_BF16(d[nt], al0, al1, al2, al3, bh0, bh1);   // h2*w1
        }
    }

    // ---- epilogue: D frag lane l holds rows (l/4, l/4+8), cols (l%4)*2,+1
    int r0 = rowbase + rb + (lane >> 2);
    int r1 = r0 + 8;
    int cl = (lane & 3) * 2;
    float pl0 = 0.f, pr0 = 0.f, pl1 = 0.f, pr1 = 0.f;
#pragma unroll
    for (int nt = 0; nt < 4; nt++) {
        int c = nt * 8 + cl;
        float a0 = __ldg(&attn_w[c]),      a1 = __ldg(&attn_w[c + 1]);
        float b0 = __ldg(&attn_w[32 + c]), b1 = __ldg(&attn_w[33 + c]);
        pl0 += d[nt][0] * a0 + d[nt][1] * a1;
        pr0 += d[nt][0] * b0 + d[nt][1] * b1;
        pl1 += d[nt][2] * a0 + d[nt][3] * a1;
        pr1 += d[nt][2] * b0 + d[nt][3] * b1;
        if (r0 < N_NODES)
            *(__half2*)&g_zh[r0 * 32 + c] = __floats2half2_rn(d[nt][0], d[nt][1]);
        if (r1 < N_NODES)
            *(__half2*)&g_zh[r1 * 32 + c] = __floats2half2_rn(d[nt][2], d[nt][3]);
    }
    // reduce over the 4 lanes sharing a row (lane^1, lane^2 keep l/4)
#pragma unroll
    for (int o = 1; o < 4; o <<= 1) {
        pl0 += __shfl_xor_sync(0xffffffffu, pl0, o);
        pr0 += __shfl_xor_sync(0xffffffffu, pr0, o);
        pl1 += __shfl_xor_sync(0xffffffffu, pl1, o);
        pr1 += __shfl_xor_sync(0xffffffffu, pr1, o);
    }
    if ((lane & 3) == 0) {
        if (r0 < N_NODES) { g_sl[r0] = pl0; g_sr[r0] = pr0; }
        if (r1 < N_NODES) { g_sl[r1] = pl1; g_sr[r1] = pr1; }
    }
}

// ---------------------------------------------------------------------------
// scatter: w = exp(leaky_relu(s_l[src]+s_r[dst])) (no max subtraction —
// mathematically identical softmax; |e| bounded ~20 so exp is safe in fp32).
// ---------------------------------------------------------------------------
__device__ __forceinline__ void scatter_one(int s, int d) {
    float e = g_sl[s] + g_sr[d];
    e = (e > 0.0f) ? e : 0.01f * e;
    float w = __expf(e);
    int local = atomicAdd(&g_cnt[d], 1);
    if (local < CAP)
        g_pk[d * CAP + local] = make_uint2((unsigned)s, __float_as_uint(w));
}

__global__ void scatter_kernel(const int* __restrict__ src,
                               const int* __restrict__ dst) {
    int i = blockIdx.x * blockDim.x + threadIdx.x;
    if (i >= E_EDGES / 4) return;
    int4 s4 = ((const int4*)src)[i];
    int4 d4 = ((const int4*)dst)[i];
    scatter_one(s4.x, d4.x);
    scatter_one(s4.y, d4.y);
    scatter_one(s4.z, d4.z);
    scatter_one(s4.w, d4.w);
}

// ---------------------------------------------------------------------------
// aggregate: 2 nodes per warp; half-warp per node, each lane owns 2 cols
// via half2. z rows are 64B (fp16) -> fully coalesced per half-warp.
// ---------------------------------------------------------------------------
__global__ void agg_kernel(float* __restrict__ out) {
    int warp  = blockIdx.x * 8 + (threadIdx.x >> 5);  // 6250*8 = 50000 warps
    int lane  = threadIdx.x & 31;
    int node  = warp * 2 + (lane >> 4);               // 2 nodes per warp
    int lanec = lane & 15;                            // half2 column index

    int cnt = g_cnt[node];
    if (cnt > CAP) cnt = CAP;
    const uint2* row = &g_pk[node * CAP];
    const __half2* zb = (const __half2*)g_zh;

    float ax = 0.f, ay = 0.f, den = 0.f;
    int j = 0;
    for (; j + 4 <= cnt; j += 4) {
        uint4 q0 = __ldg((const uint4*)&row[j]);       // slots j, j+1
        uint4 q1 = __ldg((const uint4*)&row[j + 2]);   // slots j+2, j+3
        float2 z0 = __half22float2(zb[q0.x * 16 + lanec]);
        float2 z1 = __half22float2(zb[q0.z * 16 + lanec]);
        float2 z2 = __half22float2(zb[q1.x * 16 + lanec]);
        float2 z3 = __half22float2(zb[q1.z * 16 + lanec]);
        float w0 = __uint_as_float(q0.y), w1 = __uint_as_float(q0.w);
        float w2 = __uint_as_float(q1.y), w3 = __uint_as_float(q1.w);
        den += (w0 + w1) + (w2 + w3);
        ax += w0 * z0.x; ay += w0 * z0.y;
        ax += w1 * z1.x; ay += w1 * z1.y;
        ax += w2 * z2.x; ay += w2 * z2.y;
        ax += w3 * z3.x; ay += w3 * z3.y;
    }
    for (; j < cnt; j++) {
        uint2 p = __ldg(&row[j]);
        float w = __uint_as_float(p.y);
        float2 z = __half22float2(zb[p.x * 16 + lanec]);
        den += w;
        ax += w * z.x;
        ay += w * z.y;
    }
    float inv = (cnt > 0) ? 1.0f / den : 0.0f;
    *(float2*)&out[node * 32 + lanec * 2] = make_float2(ax * inv, ay * inv);
}

// ---------------------------------------------------------------------------
extern "C" void kernel_launch(void* const* d_in, const int* in_sizes, int n_in,
                              void* d_out, int out_size) {
    const float* h      = (const float*)d_in[0];
    const int*   src    = (const int*)d_in[1];
    const int*   dst    = (const int*)d_in[2];
    const float* fc_w   = (const float*)d_in[3];
    const float* attn_w = (const float*)d_in[4];
    float* out = (float*)d_out;

    gemm_kernel   <<<1563, 128>>>(h, fc_w, attn_w);
    scatter_kernel<<<1563, 256>>>(src, dst);
    agg_kernel    <<<6250, 256>>>(out);
}